// round 5
// baseline (speedup 1.0000x reference)
#include <cuda_runtime.h>
#include <cstdint>

// Problem constants
#define BB 4096
#define SS 200
#define DD 64
#define HH 36
#define NROWS (BB*SS)          // 819200
#define ROWF  (SS*HH)          // 7200 floats of h per batch

// ---------------- device scratch (no allocations allowed) ----------------
// h stored TRANSPOSED per batch: g_h[b*7200 + j*200 + s]
__device__ float g_h[(size_t)NROWS * HH];     // 118 MB staged h^T
__device__ float g_part[BB * 72];             // per-block [sum(36), sumsq(36)]
__device__ float g_stats[72];                 // reduced sums

// packed fp32x2 FMA (FFMA2) — double-rate fp32 on sm_103a
__device__ __forceinline__ void ffma2(unsigned long long& d,
                                      unsigned long long a,
                                      unsigned long long b) {
    asm("fma.rn.f32x2 %0, %1, %2, %0;" : "+l"(d) : "l"(a), "l"(b));
}

// ---------------- pass 1: per-batch GEMM h = hist @ M_b + u_b -------------
// grid = 4096 blocks (1 batch each), 192 threads.
// Row-pair FFMA2 (no splat ALU): a = {hist[2p][k], hist[2p+1][k]} via LDS.64,
// b = {M[k][j], M[k][j]} pre-splatted in smem via LDS.128 (2 cols/load).
// k-split into 2 stages of 32 keeps smem at 44.7KB -> 4 CTAs/SM.
// SMEM: hp [32][202] f32 (25,856) | msp float2[64][36] (18,432) | u[36] | cbuf[64]
#define HP_STRIDE_F 202
#define HP_STRIDE_U 101
#define MSP_OFF   25856
#define U_OFF     44288
#define CB_OFF    44432
#define SMEM1     44688

__global__ void __launch_bounds__(192, 4)
pass1_kernel(const float* __restrict__ hist,
             const float* __restrict__ cand,
             const float* __restrict__ W1,
             const float* __restrict__ b1)
{
    extern __shared__ unsigned char smem_raw[];
    float*  hpF  = (float*)smem_raw;
    const unsigned long long* hpU = (const unsigned long long*)smem_raw;
    float2* msp2 = (float2*)(smem_raw + MSP_OFF);
    float*  u    = (float*)(smem_raw + U_OFF);
    float*  cbuf = (float*)(smem_raw + CB_OFF);

    const int tid = threadIdx.x;
    const int b   = blockIdx.x;
    const float* hb = hist + (size_t)b * (SS * DD);

    if (tid < 64) cbuf[tid] = cand[b * 64 + tid];
    __syncthreads();

    // M splat pairs: msp[k][j] = {M,M}, M = W1[64+k][j]-W1[128+k][j]+cand[k]*W1[192+k][j]
    for (int e = tid; e < 64 * 36; e += 192) {
        int k = e / 36;
        float m = W1[2304 + e] - W1[4608 + e] + cbuf[k] * W1[6912 + e];
        msp2[e] = make_float2(m, m);
    }
    // u[j] = b1[j] + sum_k cand[k]*(W1[k][j] + W1[128+k][j])
    if (tid < 36) {
        int j = tid;
        float a = b1[j];
        #pragma unroll 8
        for (int k = 0; k < 64; k++)
            a += cbuf[k] * (W1[k * 36 + j] + W1[(128 + k) * 36 + j]);
        u[j] = a;
    }

    // warp w owns cols [6w, 6w+6); lane l (<25) owns row-pairs p = i*25+l (i=0..3)
    const int w  = tid >> 5;
    const int l  = tid & 31;
    const int jc = w * 6;
    const bool act = (l < 25);

    unsigned long long acc[4][6];
    #pragma unroll
    for (int i = 0; i < 4; i++)
        #pragma unroll
        for (int j = 0; j < 6; j++) acc[i][j] = 0ull;

    // two k-stages of 32 over the half-size hp tile
    for (int st = 0; st < 2; st++) {
        const int kk0 = st * 32;
        // transpose this k-half: hp[k][s] = hist[s][kk0+k]
        {
            const float4* h4 = (const float4*)hb;
            for (int f = tid; f < 1600; f += 192) {
                int s = f >> 3, q = f & 7;
                float4 v = h4[s * 16 + (kk0 >> 2) + q];
                float* base = hpF + (q * 4) * HP_STRIDE_F + s;
                base[0]                 = v.x;
                base[HP_STRIDE_F]       = v.y;
                base[2 * HP_STRIDE_F]   = v.z;
                base[3 * HP_STRIDE_F]   = v.w;
            }
        }
        __syncthreads();
        if (act) {
            #pragma unroll 2
            for (int k = 0; k < 32; k++) {
                const unsigned long long* hrow = hpU + k * HP_STRIDE_U;
                unsigned long long h0 = hrow[l];
                unsigned long long h1 = hrow[25 + l];
                unsigned long long h2 = hrow[50 + l];
                unsigned long long h3 = hrow[75 + l];
                const ulonglong2* mp =
                    (const ulonglong2*)(msp2 + (kk0 + k) * 36 + jc);
                ulonglong2 mA = mp[0];
                ulonglong2 mB = mp[1];
                ulonglong2 mC = mp[2];
                unsigned long long mm[6] = {mA.x, mA.y, mB.x, mB.y, mC.x, mC.y};
                #pragma unroll
                for (int j = 0; j < 6; j++) {
                    ffma2(acc[0][j], h0, mm[j]);
                    ffma2(acc[1][j], h1, mm[j]);
                    ffma2(acc[2][j], h2, mm[j]);
                    ffma2(acc[3][j], h3, mm[j]);
                }
            }
        }
        __syncthreads();
    }

    // epilogue per column: bias, stats, coalesced float2 store of h^T
    float* dst = g_h + (size_t)b * ROWF;
    #pragma unroll
    for (int j = 0; j < 6; j++) {
        float s1 = 0.f, s2 = 0.f;
        if (act) {
            const float uj = u[jc + j];
            #pragma unroll
            for (int i = 0; i < 4; i++) {
                float lo = __uint_as_float((unsigned)(acc[i][j] & 0xffffffffull)) + uj;
                float hi = __uint_as_float((unsigned)(acc[i][j] >> 32)) + uj;
                s1 += lo + hi;
                s2 += lo * lo + hi * hi;
                *(float2*)(dst + (jc + j) * SS + 2 * (i * 25 + l)) =
                    make_float2(lo, hi);
            }
        }
        #pragma unroll
        for (int off = 16; off > 0; off >>= 1) {
            s1 += __shfl_down_sync(0xffffffffu, s1, off);
            s2 += __shfl_down_sync(0xffffffffu, s2, off);
        }
        if (l == 0) {
            g_part[b * 72 + jc + j]      = s1;
            g_part[b * 72 + 36 + jc + j] = s2;
        }
    }
}

// ---------------- pass 2: reduce stat partials (deterministic) ------------
__global__ void __launch_bounds__(256)
reduce_stats_kernel()
{
    __shared__ float red[256];
    const int r   = blockIdx.x;      // 0..71
    const int tid = threadIdx.x;
    float s = 0.f;
    for (int b = tid; b < BB; b += 256) s += g_part[b * 72 + r];
    red[tid] = s;
    __syncthreads();
    #pragma unroll
    for (int o = 128; o > 0; o >>= 1) {
        if (tid < o) red[tid] += red[tid + o];
        __syncthreads();
    }
    if (tid == 0) g_stats[r] = red[0];
}

// ---------------- pass 3: BN + Dice + W2 + weighted pooling ---------------
// (reverted to the proven R3 version)
__global__ void __launch_bounds__(256)
pass3_kernel(const float* __restrict__ hist,
             const float* __restrict__ gamma,
             const float* __restrict__ beta,
             const float* __restrict__ alpha,
             const float* __restrict__ W2,
             const float* __restrict__ b2,
             float* __restrict__ out)
{
    __shared__ float wrow[SS];
    __shared__ float acoef[36], ccoef[36], w2s[36];
    __shared__ float pool[256];

    const int tid = threadIdx.x;
    const int b   = blockIdx.x;

    if (tid < 36) {
        float sm = g_stats[tid];
        float sq = g_stats[36 + tid];
        const float invN = 1.0f / (float)NROWS;
        float mu   = sm * invN;
        float var  = sq * invN - mu * mu;
        float rstd = rsqrtf(var + 1e-5f);
        float a    = gamma[tid] * rstd;
        acoef[tid] = a;
        ccoef[tid] = beta[tid] - mu * a;
        w2s[tid]   = W2[tid];
    }
    const float alph = alpha[0];
    const float b2v  = b2[0];
    __syncthreads();

    if (tid < SS) {
        const int s = tid;
        const float* hT = g_h + (size_t)b * ROWF;  // [j][s]
        float hn[36];
        float mean = 0.f;
        #pragma unroll
        for (int j = 0; j < 36; j++) {
            float v = acoef[j] * __ldg(hT + j * SS + s) + ccoef[j];
            hn[j] = v;
            mean += v;
        }
        mean *= (1.0f / 36.0f);
        float var = 0.f;
        #pragma unroll
        for (int j = 0; j < 36; j++) {
            float d = hn[j] - mean;
            var += d * d;
        }
        var *= (1.0f / 36.0f);
        float rs = rsqrtf(var + 1e-3f);
        float wa = 0.f;
        #pragma unroll
        for (int j = 0; j < 36; j++) {
            float x  = (hn[j] - mean) * rs;
            float ps = 1.0f / (1.0f + __expf(-x));
            float hv = hn[j] * (ps + (1.0f - ps) * alph);
            wa += hv * w2s[j];
        }
        wrow[s] = wa + b2v;
    }
    __syncthreads();

    // weighted pooling: out[b][d] = sum_s wrow[s] * hist[b][s][d]
    const float* hb = hist + (size_t)b * (SS * DD);
    const int d = tid & 63;
    const int q = tid >> 6;            // 0..3
    float acc = 0.f;
    for (int s = q; s < SS; s += 4)
        acc += wrow[s] * hb[s * 64 + d];
    pool[tid] = acc;
    __syncthreads();
    if (tid < 64)
        out[b * 64 + tid] = pool[tid] + pool[64 + tid] + pool[128 + tid] + pool[192 + tid];
}

// ---------------- launch ----------------
extern "C" void kernel_launch(void* const* d_in, const int* in_sizes, int n_in,
                              void* d_out, int out_size)
{
    const float* history = (const float*)d_in[0];
    const float* cand    = (const float*)d_in[1];
    const float* W1      = (const float*)d_in[2];
    const float* b1      = (const float*)d_in[3];
    const float* gamma   = (const float*)d_in[4];
    const float* beta    = (const float*)d_in[5];
    const float* alpha   = (const float*)d_in[6];
    const float* W2      = (const float*)d_in[7];
    const float* b2      = (const float*)d_in[8];
    float* out = (float*)d_out;

    cudaFuncSetAttribute(pass1_kernel,
                         cudaFuncAttributeMaxDynamicSharedMemorySize, SMEM1);

    pass1_kernel<<<BB, 192, SMEM1>>>(history, cand, W1, b1);
    reduce_stats_kernel<<<72, 256>>>();
    pass3_kernel<<<BB, 256>>>(history, gamma, beta, alpha, W2, b2, out);
}

// round 6
// speedup vs baseline: 1.2147x; 1.2147x over previous
#include <cuda_runtime.h>
#include <cstdint>

// Problem constants
#define BB 4096
#define SS 200
#define DD 64
#define HH 36
#define NROWS (BB*SS)          // 819200
#define ROWF  (SS*HH)          // 7200 floats of h per batch

// ---------------- device scratch (no allocations allowed) ----------------
// h stored TRANSPOSED per batch: g_h[b*7200 + j*200 + s]
__device__ float g_h[(size_t)NROWS * HH];     // 118 MB staged h^T
__device__ float g_part[BB * 144];            // per-block per-rowgroup [sum36|sq36]
__device__ float g_stats[72];                 // reduced sums

// packed fp32x2 FMA (FFMA2) — double-rate fp32 on sm_103a
__device__ __forceinline__ void ffma2(unsigned long long& d,
                                      unsigned long long a,
                                      unsigned long long b) {
    asm("fma.rn.f32x2 %0, %1, %2, %0;" : "+l"(d) : "l"(a), "l"(b));
}
// splat one f32 into both halves of a packed f32x2
__device__ __forceinline__ unsigned long long splat2(float h) {
    unsigned long long r;
    unsigned int hu = __float_as_uint(h);
    asm("mov.b64 %0, {%1, %1};" : "=l"(r) : "r"(hu));
    return r;
}

// ---------------- pass 1: per-batch GEMM h = hist @ M_b + u_b -------------
// grid = 4096 blocks (1 batch each), 192 threads, col-pair FFMA2 scheme.
// SMEM (35,344 B): hp half-tile [32][201] f32 | M [64][36] f32 | u[36] | cbuf[64]
#define HP_STRIDE 201
#define MS_OFF    25728
#define U_OFF     34944
#define CB_OFF    35088
#define SMEM1     35344

__global__ void __launch_bounds__(192, 4)
pass1_kernel(const float* __restrict__ hist,
             const float* __restrict__ cand,
             const float* __restrict__ W1,
             const float* __restrict__ b1)
{
    extern __shared__ unsigned char smem_raw[];
    float* hpF  = (float*)smem_raw;
    float* msm  = (float*)(smem_raw + MS_OFF);
    float* u    = (float*)(smem_raw + U_OFF);
    float* cbuf = (float*)(smem_raw + CB_OFF);

    const int tid = threadIdx.x;
    const int b   = blockIdx.x;
    const float* hb = hist + (size_t)b * (SS * DD);

    if (tid < 64) cbuf[tid] = cand[b * 64 + tid];
    __syncthreads();

    // M[k][j] = W1[64+k][j] - W1[128+k][j] + cand[k]*W1[192+k][j]  (unsplatted)
    for (int e = tid; e < 64 * 36; e += 192) {
        int k = e / 36;
        msm[e] = W1[2304 + e] - W1[4608 + e] + cbuf[k] * W1[6912 + e];
    }
    // u[j] = b1[j] + sum_k cand[k]*(W1[k][j] + W1[128+k][j])
    if (tid < 36) {
        int j = tid;
        float a = b1[j];
        #pragma unroll 8
        for (int k = 0; k < 64; k++)
            a += cbuf[k] * (W1[k * 36 + j] + W1[(128 + k) * 36 + j]);
        u[j] = a;
    }

    // warp tiling: w = wr*3 + wc ; wr = row-group (100 rows), wc = 12 cols
    const int w  = tid >> 5;
    const int l  = tid & 31;
    const int wc = w % 3;
    const int wr = w / 3;
    const int jc = wc * 12;
    const int rowbase = wr * 100;
    const bool act = (l < 25);

    unsigned long long acc[4][6];
    #pragma unroll
    for (int i = 0; i < 4; i++)
        #pragma unroll
        for (int j = 0; j < 6; j++) acc[i][j] = 0ull;

    // two k-stages of 32 over a half-size hp tile
    for (int st = 0; st < 2; st++) {
        const int kk0 = st * 32;
        // load+transpose this half: hp[k][s] = hist[s][kk0+k]
        {
            const float4* h4 = (const float4*)hb;
            for (int f = tid; f < 1600; f += 192) {
                int s = f >> 3, q = f & 7;
                float4 v = h4[s * 16 + (kk0 >> 2) + q];
                float* base = hpF + (q * 4) * HP_STRIDE + s;
                base[0]              = v.x;
                base[HP_STRIDE]      = v.y;
                base[2 * HP_STRIDE]  = v.z;
                base[3 * HP_STRIDE]  = v.w;
            }
        }
        __syncthreads();
        if (act) {
            #pragma unroll 2
            for (int k = 0; k < 32; k++) {
                const float* hrow = hpF + k * HP_STRIDE + rowbase + l;
                unsigned long long h0 = splat2(hrow[0]);
                unsigned long long h1 = splat2(hrow[25]);
                unsigned long long h2 = splat2(hrow[50]);
                unsigned long long h3 = splat2(hrow[75]);
                const ulonglong2* mp = (const ulonglong2*)(msm + (kk0 + k) * 36 + jc);
                ulonglong2 mA = mp[0];
                ulonglong2 mB = mp[1];
                ulonglong2 mC = mp[2];
                unsigned long long mm[6] = {mA.x, mA.y, mB.x, mB.y, mC.x, mC.y};
                #pragma unroll
                for (int j = 0; j < 6; j++) {
                    ffma2(acc[0][j], h0, mm[j]);
                    ffma2(acc[1][j], h1, mm[j]);
                    ffma2(acc[2][j], h2, mm[j]);
                    ffma2(acc[3][j], h3, mm[j]);
                }
            }
        }
        __syncthreads();
    }

    // epilogue per column-pair: bias, stats, store h^T (coalesced STG.32)
    float* dst = g_h + (size_t)b * ROWF;
    const int pbase = b * 144 + wr * 72;
    #pragma unroll
    for (int j = 0; j < 6; j++) {
        float sLo = 0.f, sHi = 0.f, qLo = 0.f, qHi = 0.f;
        if (act) {
            const float uLo = u[jc + 2 * j];
            const float uHi = u[jc + 2 * j + 1];
            #pragma unroll
            for (int i = 0; i < 4; i++) {
                float lo = __uint_as_float((unsigned)(acc[i][j] & 0xffffffffull)) + uLo;
                float hi = __uint_as_float((unsigned)(acc[i][j] >> 32)) + uHi;
                sLo += lo; qLo += lo * lo;
                sHi += hi; qHi += hi * hi;
                int row = rowbase + i * 25 + l;
                dst[(jc + 2 * j) * SS + row]     = lo;
                dst[(jc + 2 * j + 1) * SS + row] = hi;
            }
        }
        #pragma unroll
        for (int off = 16; off > 0; off >>= 1) {
            sLo += __shfl_down_sync(0xffffffffu, sLo, off);
            qLo += __shfl_down_sync(0xffffffffu, qLo, off);
            sHi += __shfl_down_sync(0xffffffffu, sHi, off);
            qHi += __shfl_down_sync(0xffffffffu, qHi, off);
        }
        if (l == 0) {
            g_part[pbase + jc + 2 * j]          = sLo;
            g_part[pbase + 36 + jc + 2 * j]     = qLo;
            g_part[pbase + jc + 2 * j + 1]      = sHi;
            g_part[pbase + 36 + jc + 2 * j + 1] = qHi;
        }
    }
}

// ---------------- pass 2: reduce stat partials (deterministic) ------------
__global__ void __launch_bounds__(256)
reduce_stats_kernel()
{
    __shared__ float red[256];
    const int r   = blockIdx.x;      // 0..71
    const int tid = threadIdx.x;
    float s = 0.f;
    for (int b = tid; b < BB; b += 256)
        s += g_part[b * 144 + r] + g_part[b * 144 + 72 + r];
    red[tid] = s;
    __syncthreads();
    #pragma unroll
    for (int o = 128; o > 0; o >>= 1) {
        if (tid < o) red[tid] += red[tid + o];
        __syncthreads();
    }
    if (tid == 0) g_stats[r] = red[0];
}

// ---------------- pass 3: BN + Dice + W2 + weighted pooling ---------------
// (the proven R3 version, verbatim)
__global__ void __launch_bounds__(256)
pass3_kernel(const float* __restrict__ hist,
             const float* __restrict__ gamma,
             const float* __restrict__ beta,
             const float* __restrict__ alpha,
             const float* __restrict__ W2,
             const float* __restrict__ b2,
             float* __restrict__ out)
{
    __shared__ float wrow[SS];
    __shared__ float acoef[36], ccoef[36], w2s[36];
    __shared__ float pool[256];

    const int tid = threadIdx.x;
    const int b   = blockIdx.x;

    if (tid < 36) {
        float sm = g_stats[tid];
        float sq = g_stats[36 + tid];
        const float invN = 1.0f / (float)NROWS;
        float mu   = sm * invN;
        float var  = sq * invN - mu * mu;
        float rstd = rsqrtf(var + 1e-5f);
        float a    = gamma[tid] * rstd;
        acoef[tid] = a;
        ccoef[tid] = beta[tid] - mu * a;
        w2s[tid]   = W2[tid];
    }
    const float alph = alpha[0];
    const float b2v  = b2[0];
    __syncthreads();

    if (tid < SS) {
        const int s = tid;
        const float* hT = g_h + (size_t)b * ROWF;  // [j][s]
        float hn[36];
        float mean = 0.f;
        #pragma unroll
        for (int j = 0; j < 36; j++) {
            float v = acoef[j] * __ldg(hT + j * SS + s) + ccoef[j];
            hn[j] = v;
            mean += v;
        }
        mean *= (1.0f / 36.0f);
        float var = 0.f;
        #pragma unroll
        for (int j = 0; j < 36; j++) {
            float d = hn[j] - mean;
            var += d * d;
        }
        var *= (1.0f / 36.0f);
        float rs = rsqrtf(var + 1e-3f);
        float wa = 0.f;
        #pragma unroll
        for (int j = 0; j < 36; j++) {
            float x  = (hn[j] - mean) * rs;
            float ps = 1.0f / (1.0f + __expf(-x));
            float hv = hn[j] * (ps + (1.0f - ps) * alph);
            wa += hv * w2s[j];
        }
        wrow[s] = wa + b2v;
    }
    __syncthreads();

    // weighted pooling: out[b][d] = sum_s wrow[s] * hist[b][s][d]
    const float* hb = hist + (size_t)b * (SS * DD);
    const int d = tid & 63;
    const int q = tid >> 6;            // 0..3
    float acc = 0.f;
    for (int s = q; s < SS; s += 4)
        acc += wrow[s] * hb[s * 64 + d];
    pool[tid] = acc;
    __syncthreads();
    if (tid < 64)
        out[b * 64 + tid] = pool[tid] + pool[64 + tid] + pool[128 + tid] + pool[192 + tid];
}

// ---------------- launch ----------------
extern "C" void kernel_launch(void* const* d_in, const int* in_sizes, int n_in,
                              void* d_out, int out_size)
{
    const float* history = (const float*)d_in[0];
    const float* cand    = (const float*)d_in[1];
    const float* W1      = (const float*)d_in[2];
    const float* b1      = (const float*)d_in[3];
    const float* gamma   = (const float*)d_in[4];
    const float* beta    = (const float*)d_in[5];
    const float* alpha   = (const float*)d_in[6];
    const float* W2      = (const float*)d_in[7];
    const float* b2      = (const float*)d_in[8];
    float* out = (float*)d_out;

    cudaFuncSetAttribute(pass1_kernel,
                         cudaFuncAttributeMaxDynamicSharedMemorySize, SMEM1);

    pass1_kernel<<<BB, 192, SMEM1>>>(history, cand, W1, b1);
    reduce_stats_kernel<<<72, 256>>>();
    pass3_kernel<<<BB, 256>>>(history, gamma, beta, alpha, W2, b2, out);
}

// round 7
// speedup vs baseline: 1.3551x; 1.1155x over previous
#include <cuda_runtime.h>
#include <cstdint>

// Problem constants
#define BB 4096
#define SS 200
#define DD 64
#define HH 36
#define NROWS (BB*SS)          // 819200
#define ROWF  (SS*HH)          // 7200 floats of h per batch

// ---------------- device scratch (no allocations allowed) ----------------
// h stored TRANSPOSED per batch: g_h[b*7200 + j*200 + s]
__device__ float g_h[(size_t)NROWS * HH];     // 118 MB staged h^T
__device__ float g_part[BB * 144];            // per-block per-rowgroup [sum36|sq36]
__device__ float g_stats[72];                 // reduced sums

// packed fp32x2 FMA (FFMA2) — double-rate fp32 on sm_103a
__device__ __forceinline__ void ffma2(unsigned long long& d,
                                      unsigned long long a,
                                      unsigned long long b) {
    asm("fma.rn.f32x2 %0, %1, %2, %0;" : "+l"(d) : "l"(a), "l"(b));
}
// splat one f32 into both halves of a packed f32x2
__device__ __forceinline__ unsigned long long splat2(float h) {
    unsigned long long r;
    unsigned int hu = __float_as_uint(h);
    asm("mov.b64 %0, {%1, %1};" : "=l"(r) : "r"(hu));
    return r;
}
// 4-byte async copy global->shared (LDGSTS)
__device__ __forceinline__ void cpasync4(unsigned int dst, const float* src) {
    asm volatile("cp.async.ca.shared.global [%0], [%1], 4;"
                 :: "r"(dst), "l"(src));
}
__device__ __forceinline__ void cp_commit() {
    asm volatile("cp.async.commit_group;");
}
template <int N>
__device__ __forceinline__ void cp_wait() {
    asm volatile("cp.async.wait_group %0;" :: "n"(N));
}
__device__ __forceinline__ unsigned int smem_u32(const void* p) {
    unsigned int a;
    asm("{ .reg .u64 t; cvta.to.shared.u64 t, %1; cvt.u32.u64 %0, t; }"
        : "=r"(a) : "l"(p));
    return a;
}

// ---------------- pass 1: per-batch GEMM h = hist @ M_b + u_b -------------
// grid = 4096 blocks (1 batch each), 192 threads, col-pair FFMA2 scheme.
// hist tile staged k-major hp[s][17] (pitch 17 floats: conflict-free column
// reads), filled by cp.async 4B, 4 stages x 16 k, double buffered.
// SMEM (36,816 B): hp 2x[200][17] f32 | M[64][36] f32 | u[36] | cbuf[64]
#define HP_PITCH  17
#define HP_BUFB   13600                 // 200*17*4 bytes per buffer
#define MS_OFF    27200
#define U_OFF     36416
#define CB_OFF    36560
#define SMEM1     36816
#define KSTAGE    16                    // k per stage
#define NSTAGE    4

__global__ void __launch_bounds__(192, 4)
pass1_kernel(const float* __restrict__ hist,
             const float* __restrict__ cand,
             const float* __restrict__ W1,
             const float* __restrict__ b1)
{
    extern __shared__ unsigned char smem_raw[];
    float* hpF  = (float*)smem_raw;
    float* msm  = (float*)(smem_raw + MS_OFF);
    float* u    = (float*)(smem_raw + U_OFF);
    float* cbuf = (float*)(smem_raw + CB_OFF);

    const int tid = threadIdx.x;
    const int b   = blockIdx.x;
    const float* hb = hist + (size_t)b * (SS * DD);
    const unsigned int hp_base = smem_u32(smem_raw);

    // kick off fills for stage 0 and 1 immediately (overlaps M/u build)
    #pragma unroll
    for (int st = 0; st < 2; st++) {
        const int k0 = st * KSTAGE;
        const unsigned int dstb = hp_base + (st & 1) * HP_BUFB;
        for (int o = tid; o < SS * KSTAGE; o += 192) {
            int row = o >> 4, c = o & 15;
            cpasync4(dstb + (unsigned)(row * HP_PITCH + c) * 4,
                     hb + row * DD + k0 + c);
        }
        cp_commit();
    }

    if (tid < 64) cbuf[tid] = cand[b * 64 + tid];
    __syncthreads();

    // M[k][j] = W1[64+k][j] - W1[128+k][j] + cand[k]*W1[192+k][j]  (unsplatted)
    for (int e = tid; e < 64 * 36; e += 192) {
        int k = e / 36;
        msm[e] = W1[2304 + e] - W1[4608 + e] + cbuf[k] * W1[6912 + e];
    }
    // u[j] = b1[j] + sum_k cand[k]*(W1[k][j] + W1[128+k][j])
    if (tid < 36) {
        int j = tid;
        float a = b1[j];
        #pragma unroll 8
        for (int k = 0; k < 64; k++)
            a += cbuf[k] * (W1[k * 36 + j] + W1[(128 + k) * 36 + j]);
        u[j] = a;
    }

    // warp tiling: w = wr*3 + wc ; wr = row-group (100 rows), wc = 12 cols
    const int w  = tid >> 5;
    const int l  = tid & 31;
    const int wc = w % 3;
    const int wr = w / 3;
    const int jc = wc * 12;
    const int rowbase = wr * 100;
    const bool act = (l < 25);
    const int r0 = (rowbase + l) * HP_PITCH;

    unsigned long long acc[4][6];
    #pragma unroll
    for (int i = 0; i < 4; i++)
        #pragma unroll
        for (int j = 0; j < 6; j++) acc[i][j] = 0ull;

    // pipelined k-stages
    for (int st = 0; st < NSTAGE; st++) {
        if (st < NSTAGE - 1) cp_wait<1>(); else cp_wait<0>();
        __syncthreads();                       // stage st data visible to all

        const float* hs = hpF + (st & 1) * (HP_BUFB / 4);
        if (act) {
            const int km0 = st * KSTAGE;
            #pragma unroll 4
            for (int k = 0; k < KSTAGE; k++) {
                unsigned long long h0 = splat2(hs[r0 + k]);
                unsigned long long h1 = splat2(hs[r0 + 25 * HP_PITCH + k]);
                unsigned long long h2 = splat2(hs[r0 + 50 * HP_PITCH + k]);
                unsigned long long h3 = splat2(hs[r0 + 75 * HP_PITCH + k]);
                const ulonglong2* mp =
                    (const ulonglong2*)(msm + (km0 + k) * 36 + jc);
                ulonglong2 mA = mp[0];
                ulonglong2 mB = mp[1];
                ulonglong2 mC = mp[2];
                unsigned long long mm[6] = {mA.x, mA.y, mB.x, mB.y, mC.x, mC.y};
                #pragma unroll
                for (int j = 0; j < 6; j++) {
                    ffma2(acc[0][j], h0, mm[j]);
                    ffma2(acc[1][j], h1, mm[j]);
                    ffma2(acc[2][j], h2, mm[j]);
                    ffma2(acc[3][j], h3, mm[j]);
                }
            }
        }
        __syncthreads();                       // everyone done reading buffer
        if (st + 2 < NSTAGE) {
            const int k0 = (st + 2) * KSTAGE;
            const unsigned int dstb = hp_base + (st & 1) * HP_BUFB;
            for (int o = tid; o < SS * KSTAGE; o += 192) {
                int row = o >> 4, c = o & 15;
                cpasync4(dstb + (unsigned)(row * HP_PITCH + c) * 4,
                         hb + row * DD + k0 + c);
            }
        }
        cp_commit();                           // uniform group count per thread
    }

    // epilogue per column-pair: bias, stats, store h^T (coalesced STG.32)
    float* dst = g_h + (size_t)b * ROWF;
    const int pbase = b * 144 + wr * 72;
    #pragma unroll
    for (int j = 0; j < 6; j++) {
        float sLo = 0.f, sHi = 0.f, qLo = 0.f, qHi = 0.f;
        if (act) {
            const float uLo = u[jc + 2 * j];
            const float uHi = u[jc + 2 * j + 1];
            #pragma unroll
            for (int i = 0; i < 4; i++) {
                float lo = __uint_as_float((unsigned)(acc[i][j] & 0xffffffffull)) + uLo;
                float hi = __uint_as_float((unsigned)(acc[i][j] >> 32)) + uHi;
                sLo += lo; qLo += lo * lo;
                sHi += hi; qHi += hi * hi;
                int row = rowbase + i * 25 + l;
                dst[(jc + 2 * j) * SS + row]     = lo;
                dst[(jc + 2 * j + 1) * SS + row] = hi;
            }
        }
        #pragma unroll
        for (int off = 16; off > 0; off >>= 1) {
            sLo += __shfl_down_sync(0xffffffffu, sLo, off);
            qLo += __shfl_down_sync(0xffffffffu, qLo, off);
            sHi += __shfl_down_sync(0xffffffffu, sHi, off);
            qHi += __shfl_down_sync(0xffffffffu, qHi, off);
        }
        if (l == 0) {
            g_part[pbase + jc + 2 * j]          = sLo;
            g_part[pbase + 36 + jc + 2 * j]     = qLo;
            g_part[pbase + jc + 2 * j + 1]      = sHi;
            g_part[pbase + 36 + jc + 2 * j + 1] = qHi;
        }
    }
}

// ---------------- pass 2: reduce stat partials (deterministic) ------------
__global__ void __launch_bounds__(256)
reduce_stats_kernel()
{
    __shared__ float red[256];
    const int r   = blockIdx.x;      // 0..71
    const int tid = threadIdx.x;
    float s = 0.f;
    for (int b = tid; b < BB; b += 256)
        s += g_part[b * 144 + r] + g_part[b * 144 + 72 + r];
    red[tid] = s;
    __syncthreads();
    #pragma unroll
    for (int o = 128; o > 0; o >>= 1) {
        if (tid < o) red[tid] += red[tid + o];
        __syncthreads();
    }
    if (tid == 0) g_stats[r] = red[0];
}

// ---------------- pass 3: BN + Dice + W2 + weighted pooling ---------------
// (the proven R3 version, verbatim)
__global__ void __launch_bounds__(256)
pass3_kernel(const float* __restrict__ hist,
             const float* __restrict__ gamma,
             const float* __restrict__ beta,
             const float* __restrict__ alpha,
             const float* __restrict__ W2,
             const float* __restrict__ b2,
             float* __restrict__ out)
{
    __shared__ float wrow[SS];
    __shared__ float acoef[36], ccoef[36], w2s[36];
    __shared__ float pool[256];

    const int tid = threadIdx.x;
    const int b   = blockIdx.x;

    if (tid < 36) {
        float sm = g_stats[tid];
        float sq = g_stats[36 + tid];
        const float invN = 1.0f / (float)NROWS;
        float mu   = sm * invN;
        float var  = sq * invN - mu * mu;
        float rstd = rsqrtf(var + 1e-5f);
        float a    = gamma[tid] * rstd;
        acoef[tid] = a;
        ccoef[tid] = beta[tid] - mu * a;
        w2s[tid]   = W2[tid];
    }
    const float alph = alpha[0];
    const float b2v  = b2[0];
    __syncthreads();

    if (tid < SS) {
        const int s = tid;
        const float* hT = g_h + (size_t)b * ROWF;  // [j][s]
        float hn[36];
        float mean = 0.f;
        #pragma unroll
        for (int j = 0; j < 36; j++) {
            float v = acoef[j] * __ldg(hT + j * SS + s) + ccoef[j];
            hn[j] = v;
            mean += v;
        }
        mean *= (1.0f / 36.0f);
        float var = 0.f;
        #pragma unroll
        for (int j = 0; j < 36; j++) {
            float d = hn[j] - mean;
            var += d * d;
        }
        var *= (1.0f / 36.0f);
        float rs = rsqrtf(var + 1e-3f);
        float wa = 0.f;
        #pragma unroll
        for (int j = 0; j < 36; j++) {
            float x  = (hn[j] - mean) * rs;
            float ps = 1.0f / (1.0f + __expf(-x));
            float hv = hn[j] * (ps + (1.0f - ps) * alph);
            wa += hv * w2s[j];
        }
        wrow[s] = wa + b2v;
    }
    __syncthreads();

    // weighted pooling: out[b][d] = sum_s wrow[s] * hist[b][s][d]
    const float* hb = hist + (size_t)b * (SS * DD);
    const int d = tid & 63;
    const int q = tid >> 6;            // 0..3
    float acc = 0.f;
    for (int s = q; s < SS; s += 4)
        acc += wrow[s] * hb[s * 64 + d];
    pool[tid] = acc;
    __syncthreads();
    if (tid < 64)
        out[b * 64 + tid] = pool[tid] + pool[64 + tid] + pool[128 + tid] + pool[192 + tid];
}

// ---------------- launch ----------------
extern "C" void kernel_launch(void* const* d_in, const int* in_sizes, int n_in,
                              void* d_out, int out_size)
{
    const float* history = (const float*)d_in[0];
    const float* cand    = (const float*)d_in[1];
    const float* W1      = (const float*)d_in[2];
    const float* b1      = (const float*)d_in[3];
    const float* gamma   = (const float*)d_in[4];
    const float* beta    = (const float*)d_in[5];
    const float* alpha   = (const float*)d_in[6];
    const float* W2      = (const float*)d_in[7];
    const float* b2      = (const float*)d_in[8];
    float* out = (float*)d_out;

    cudaFuncSetAttribute(pass1_kernel,
                         cudaFuncAttributeMaxDynamicSharedMemorySize, SMEM1);

    pass1_kernel<<<BB, 192, SMEM1>>>(history, cand, W1, b1);
    reduce_stats_kernel<<<72, 256>>>();
    pass3_kernel<<<BB, 256>>>(history, gamma, beta, alpha, W2, b2, out);
}

// round 9
// speedup vs baseline: 1.4375x; 1.0608x over previous
#include <cuda_runtime.h>
#include <cstdint>

// Problem constants
#define BB 4096
#define SS 200
#define DD 64
#define HH 36
#define NROWS (BB*SS)          // 819200
#define ROWF  (SS*HH)          // 7200 floats of h per batch

// ---------------- device scratch (no allocations allowed) ----------------
// h stored TRANSPOSED per batch: g_h[b*7200 + j*200 + s]
__device__ float g_h[(size_t)NROWS * HH];     // 118 MB staged h^T
__device__ float g_part[BB * 144];            // per-block per-rowgroup [sum36|sq36]
__device__ float g_stats[72];                 // reduced sums

// packed fp32x2 FMA (FFMA2) — double-rate fp32 on sm_103a
__device__ __forceinline__ void ffma2(unsigned long long& d,
                                      unsigned long long a,
                                      unsigned long long b) {
    asm("fma.rn.f32x2 %0, %1, %2, %0;" : "+l"(d) : "l"(a), "l"(b));
}
// splat one f32 into both halves of a packed f32x2
__device__ __forceinline__ unsigned long long splat2(float h) {
    unsigned long long r;
    unsigned int hu = __float_as_uint(h);
    asm("mov.b64 %0, {%1, %1};" : "=l"(r) : "r"(hu));
    return r;
}
// 4-byte async copy global->shared (LDGSTS)
__device__ __forceinline__ void cpasync4(unsigned int dst, const float* src) {
    asm volatile("cp.async.ca.shared.global [%0], [%1], 4;"
                 :: "r"(dst), "l"(src));
}
__device__ __forceinline__ void cp_commit() {
    asm volatile("cp.async.commit_group;");
}
template <int N>
__device__ __forceinline__ void cp_wait() {
    asm volatile("cp.async.wait_group %0;" :: "n"(N));
}
__device__ __forceinline__ unsigned int smem_u32(const void* p) {
    unsigned int a;
    asm("{ .reg .u64 t; cvta.to.shared.u64 t, %1; cvt.u32.u64 %0, t; }"
        : "=r"(a) : "l"(p));
    return a;
}

// ---------------- pass 1: per-batch GEMM h = hist @ M_b + u_b -------------
// (R7 winner, byte-identical)
#define HP_PITCH  17
#define HP_BUFB   13600                 // 200*17*4 bytes per buffer
#define MS_OFF    27200
#define U_OFF     36416
#define CB_OFF    36560
#define SMEM1     36816
#define KSTAGE    16                    // k per stage
#define NSTAGE    4

__global__ void __launch_bounds__(192, 4)
pass1_kernel(const float* __restrict__ hist,
             const float* __restrict__ cand,
             const float* __restrict__ W1,
             const float* __restrict__ b1)
{
    extern __shared__ unsigned char smem_raw[];
    float* hpF  = (float*)smem_raw;
    float* msm  = (float*)(smem_raw + MS_OFF);
    float* u    = (float*)(smem_raw + U_OFF);
    float* cbuf = (float*)(smem_raw + CB_OFF);

    const int tid = threadIdx.x;
    const int b   = blockIdx.x;
    const float* hb = hist + (size_t)b * (SS * DD);
    const unsigned int hp_base = smem_u32(smem_raw);

    // kick off fills for stage 0 and 1 immediately (overlaps M/u build)
    #pragma unroll
    for (int st = 0; st < 2; st++) {
        const int k0 = st * KSTAGE;
        const unsigned int dstb = hp_base + (st & 1) * HP_BUFB;
        for (int o = tid; o < SS * KSTAGE; o += 192) {
            int row = o >> 4, c = o & 15;
            cpasync4(dstb + (unsigned)(row * HP_PITCH + c) * 4,
                     hb + row * DD + k0 + c);
        }
        cp_commit();
    }

    if (tid < 64) cbuf[tid] = cand[b * 64 + tid];
    __syncthreads();

    // M[k][j] = W1[64+k][j] - W1[128+k][j] + cand[k]*W1[192+k][j]  (unsplatted)
    for (int e = tid; e < 64 * 36; e += 192) {
        int k = e / 36;
        msm[e] = W1[2304 + e] - W1[4608 + e] + cbuf[k] * W1[6912 + e];
    }
    // u[j] = b1[j] + sum_k cand[k]*(W1[k][j] + W1[128+k][j])
    if (tid < 36) {
        int j = tid;
        float a = b1[j];
        #pragma unroll 8
        for (int k = 0; k < 64; k++)
            a += cbuf[k] * (W1[k * 36 + j] + W1[(128 + k) * 36 + j]);
        u[j] = a;
    }

    // warp tiling: w = wr*3 + wc ; wr = row-group (100 rows), wc = 12 cols
    const int w  = tid >> 5;
    const int l  = tid & 31;
    const int wc = w % 3;
    const int wr = w / 3;
    const int jc = wc * 12;
    const int rowbase = wr * 100;
    const bool act = (l < 25);
    const int r0 = (rowbase + l) * HP_PITCH;

    unsigned long long acc[4][6];
    #pragma unroll
    for (int i = 0; i < 4; i++)
        #pragma unroll
        for (int j = 0; j < 6; j++) acc[i][j] = 0ull;

    // pipelined k-stages
    for (int st = 0; st < NSTAGE; st++) {
        if (st < NSTAGE - 1) cp_wait<1>(); else cp_wait<0>();
        __syncthreads();                       // stage st data visible to all

        const float* hs = hpF + (st & 1) * (HP_BUFB / 4);
        if (act) {
            const int km0 = st * KSTAGE;
            #pragma unroll 4
            for (int k = 0; k < KSTAGE; k++) {
                unsigned long long h0 = splat2(hs[r0 + k]);
                unsigned long long h1 = splat2(hs[r0 + 25 * HP_PITCH + k]);
                unsigned long long h2 = splat2(hs[r0 + 50 * HP_PITCH + k]);
                unsigned long long h3 = splat2(hs[r0 + 75 * HP_PITCH + k]);
                const ulonglong2* mp =
                    (const ulonglong2*)(msm + (km0 + k) * 36 + jc);
                ulonglong2 mA = mp[0];
                ulonglong2 mB = mp[1];
                ulonglong2 mC = mp[2];
                unsigned long long mm[6] = {mA.x, mA.y, mB.x, mB.y, mC.x, mC.y};
                #pragma unroll
                for (int j = 0; j < 6; j++) {
                    ffma2(acc[0][j], h0, mm[j]);
                    ffma2(acc[1][j], h1, mm[j]);
                    ffma2(acc[2][j], h2, mm[j]);
                    ffma2(acc[3][j], h3, mm[j]);
                }
            }
        }
        __syncthreads();                       // everyone done reading buffer
        if (st + 2 < NSTAGE) {
            const int k0 = (st + 2) * KSTAGE;
            const unsigned int dstb = hp_base + (st & 1) * HP_BUFB;
            for (int o = tid; o < SS * KSTAGE; o += 192) {
                int row = o >> 4, c = o & 15;
                cpasync4(dstb + (unsigned)(row * HP_PITCH + c) * 4,
                         hb + row * DD + k0 + c);
            }
        }
        cp_commit();                           // uniform group count per thread
    }

    // epilogue per column-pair: bias, stats, store h^T (coalesced STG.32)
    float* dst = g_h + (size_t)b * ROWF;
    const int pbase = b * 144 + wr * 72;
    #pragma unroll
    for (int j = 0; j < 6; j++) {
        float sLo = 0.f, sHi = 0.f, qLo = 0.f, qHi = 0.f;
        if (act) {
            const float uLo = u[jc + 2 * j];
            const float uHi = u[jc + 2 * j + 1];
            #pragma unroll
            for (int i = 0; i < 4; i++) {
                float lo = __uint_as_float((unsigned)(acc[i][j] & 0xffffffffull)) + uLo;
                float hi = __uint_as_float((unsigned)(acc[i][j] >> 32)) + uHi;
                sLo += lo; qLo += lo * lo;
                sHi += hi; qHi += hi * hi;
                int row = rowbase + i * 25 + l;
                dst[(jc + 2 * j) * SS + row]     = lo;
                dst[(jc + 2 * j + 1) * SS + row] = hi;
            }
        }
        #pragma unroll
        for (int off = 16; off > 0; off >>= 1) {
            sLo += __shfl_down_sync(0xffffffffu, sLo, off);
            qLo += __shfl_down_sync(0xffffffffu, qLo, off);
            sHi += __shfl_down_sync(0xffffffffu, sHi, off);
            qHi += __shfl_down_sync(0xffffffffu, qHi, off);
        }
        if (l == 0) {
            g_part[pbase + jc + 2 * j]          = sLo;
            g_part[pbase + 36 + jc + 2 * j]     = qLo;
            g_part[pbase + jc + 2 * j + 1]      = sHi;
            g_part[pbase + 36 + jc + 2 * j + 1] = qHi;
        }
    }
}

// ---------------- pass 2: reduce stat partials (deterministic) ------------
__global__ void __launch_bounds__(256)
reduce_stats_kernel()
{
    __shared__ float red[256];
    const int r   = blockIdx.x;      // 0..71
    const int tid = threadIdx.x;
    float s = 0.f;
    for (int b = tid; b < BB; b += 256)
        s += g_part[b * 144 + r] + g_part[b * 144 + 72 + r];
    red[tid] = s;
    __syncthreads();
    #pragma unroll
    for (int o = 128; o > 0; o >>= 1) {
        if (tid < o) red[tid] += red[tid + o];
        __syncthreads();
    }
    if (tid == 0) g_stats[r] = red[0];
}

// ---------------- pass 3: BN + Dice + W2 + weighted pooling ---------------
// smem-staged h^T tile (float4 coalesced, FIXED bounds), single-pass stats
// (no hn[36] register array), R3-verbatim pooling.
__global__ void __launch_bounds__(256)
pass3_kernel(const float* __restrict__ hist,
             const float* __restrict__ gamma,
             const float* __restrict__ beta,
             const float* __restrict__ alpha,
             const float* __restrict__ W2,
             const float* __restrict__ b2,
             float* __restrict__ out)
{
    __shared__ float htile[ROWF];      // 28,800 B, h^T [j][s] contiguous
    __shared__ float wrow[SS];
    __shared__ float acoef[36], ccoef[36], w2s[36];
    __shared__ float pool[256];

    const int tid = threadIdx.x;
    const int b   = blockIdx.x;

    // coalesced float4 load of this batch's h^T tile (1800 float4s)
    {
        const float4* src4 = (const float4*)(g_h + (size_t)b * ROWF);
        float4* ht4 = (float4*)htile;
        for (int i = tid; i < ROWF / 4; i += 256) ht4[i] = src4[i];
    }

    if (tid < 36) {
        float sm = g_stats[tid];
        float sq = g_stats[36 + tid];
        const float invN = 1.0f / (float)NROWS;
        float mu   = sm * invN;
        float var  = sq * invN - mu * mu;
        float rstd = rsqrtf(var + 1e-5f);
        float a    = gamma[tid] * rstd;
        acoef[tid] = a;
        ccoef[tid] = beta[tid] - mu * a;
        w2s[tid]   = W2[tid];
    }
    const float alph = alpha[0];
    const float b2v  = b2[0];
    __syncthreads();

    if (tid < SS) {
        const int s = tid;
        // pass A: per-row mean & variance of BN-transformed values
        float sum = 0.f, ssq = 0.f;
        #pragma unroll
        for (int j = 0; j < 36; j++) {
            float v = acoef[j] * htile[j * SS + s] + ccoef[j];
            sum += v;
            ssq += v * v;
        }
        float mean = sum * (1.0f / 36.0f);
        float var  = ssq * (1.0f / 36.0f) - mean * mean;
        float rs   = rsqrtf(var + 1e-3f);
        // pass B: Dice + W2 dot (recompute v from smem — LDS is cheap)
        float wa = 0.f;
        #pragma unroll
        for (int j = 0; j < 36; j++) {
            float v  = acoef[j] * htile[j * SS + s] + ccoef[j];
            float x  = (v - mean) * rs;
            float ps = 1.0f / (1.0f + __expf(-x));
            float hv = v * (ps + (1.0f - ps) * alph);
            wa += hv * w2s[j];
        }
        wrow[s] = wa + b2v;
    }
    __syncthreads();

    // weighted pooling: out[b][d] = sum_s wrow[s] * hist[b][s][d]  (R3 verbatim)
    const float* hb = hist + (size_t)b * (SS * DD);
    const int d = tid & 63;
    const int q = tid >> 6;            // 0..3
    float acc = 0.f;
    for (int s = q; s < SS; s += 4)
        acc += wrow[s] * hb[s * 64 + d];
    pool[tid] = acc;
    __syncthreads();
    if (tid < 64)
        out[b * 64 + tid] = pool[tid] + pool[64 + tid] + pool[128 + tid] + pool[192 + tid];
}

// ---------------- launch ----------------
extern "C" void kernel_launch(void* const* d_in, const int* in_sizes, int n_in,
                              void* d_out, int out_size)
{
    const float* history = (const float*)d_in[0];
    const float* cand    = (const float*)d_in[1];
    const float* W1      = (const float*)d_in[2];
    const float* b1      = (const float*)d_in[3];
    const float* gamma   = (const float*)d_in[4];
    const float* beta    = (const float*)d_in[5];
    const float* alpha   = (const float*)d_in[6];
    const float* W2      = (const float*)d_in[7];
    const float* b2      = (const float*)d_in[8];
    float* out = (float*)d_out;

    cudaFuncSetAttribute(pass1_kernel,
                         cudaFuncAttributeMaxDynamicSharedMemorySize, SMEM1);

    pass1_kernel<<<BB, 192, SMEM1>>>(history, cand, W1, b1);
    reduce_stats_kernel<<<72, 256>>>();
    pass3_kernel<<<BB, 256>>>(history, gamma, beta, alpha, W2, b2, out);
}